// round 10
// baseline (speedup 1.0000x reference)
#include <cuda_runtime.h>
#include <cuda_bf16.h>
#include <cstdint>

#define D 128
#define K 64
#define TILE 64
#define NT_MAX 3125
#define NBLK 296
#define TEMP 30.0f
#define EPSn 1e-6f
#define ITERS 11

// smem: exactly 112 KB per CTA -> 2 CTAs/SM
#define OFF_MU 0                 // MuH 16K | MuL 16K
#define OFF_X  32768             // buf b at OFF_X + b*32768 (Xh 16K | Xl 16K)
#define OFF_R  98304             // Rh 8K | Rl 8K
#define SMEM_TOTAL 114688

__device__ __align__(16) unsigned char g_x[(size_t)NT_MAX * 32768];
__device__ __align__(16) unsigned char g_mu[32768];
__device__ float g_pmean[NBLK * K * D];
__device__ float g_pcnt[NBLK * K];

__device__ __forceinline__ uint32_t smem_u32(const void* p) {
    uint32_t a;
    asm("{ .reg .u64 t; cvta.to.shared.u64 t, %1; cvt.u32.u64 %0, t; }" : "=r"(a) : "l"(p));
    return a;
}
__device__ __forceinline__ void ldsm_x4(uint32_t* r, uint32_t a) {
    asm volatile("ldmatrix.sync.aligned.m8n8.x4.shared.b16 {%0,%1,%2,%3}, [%4];"
        : "=r"(r[0]), "=r"(r[1]), "=r"(r[2]), "=r"(r[3]) : "r"(a));
}
__device__ __forceinline__ void ldsm_x4t(uint32_t* r, uint32_t a) {
    asm volatile("ldmatrix.sync.aligned.m8n8.x4.trans.shared.b16 {%0,%1,%2,%3}, [%4];"
        : "=r"(r[0]), "=r"(r[1]), "=r"(r[2]), "=r"(r[3]) : "r"(a));
}
__device__ __forceinline__ void mma_bf16(float* c, const uint32_t* a, const uint32_t* b) {
    asm volatile("mma.sync.aligned.m16n8k16.row.col.f32.bf16.bf16.f32 "
        "{%0,%1,%2,%3}, {%4,%5,%6,%7}, {%8,%9}, {%0,%1,%2,%3};"
        : "+f"(c[0]), "+f"(c[1]), "+f"(c[2]), "+f"(c[3])
        : "r"(a[0]), "r"(a[1]), "r"(a[2]), "r"(a[3]), "r"(b[0]), "r"(b[1]));
}
__device__ __forceinline__ void cp16(uint32_t dst, const void* src) {
    asm volatile("cp.async.cg.shared.global [%0], [%1], 16;" :: "r"(dst), "l"(src) : "memory");
}
#define CP_COMMIT() asm volatile("cp.async.commit_group;" ::: "memory")
#define CP_WAIT0()  asm volatile("cp.async.wait_group 0;" ::: "memory")

__device__ __forceinline__ uint32_t pack_bf16x2(__nv_bfloat16 a, __nv_bfloat16 b) {
    __nv_bfloat162 v(a, b);
    return *(uint32_t*)&v;
}

// ---------------------------------------------------------------------------
__global__ void prep_kernel(const float* __restrict__ x, int N, int rowsPad) {
    int w = (blockIdx.x * blockDim.x + threadIdx.x) >> 5;
    int lane = threadIdx.x & 31;
    if (w >= rowsPad) return;
    float4 v = make_float4(0.f, 0.f, 0.f, 0.f);
    if (w < N) {
        v = ((const float4*)(x + (size_t)w * D))[lane];
        float ss = v.x*v.x + v.y*v.y + v.z*v.z + v.w*v.w;
        #pragma unroll
        for (int o = 16; o > 0; o >>= 1) ss += __shfl_xor_sync(0xffffffffu, ss, o);
        float inv = 1.0f / (sqrtf(ss) + EPSn);
        v.x *= inv; v.y *= inv; v.z *= inv; v.w *= inv;
    }
    float f[4] = {v.x, v.y, v.z, v.w};
    __nv_bfloat16 h[4], lo[4];
    #pragma unroll
    for (int i = 0; i < 4; i++) {
        h[i]  = __float2bfloat16(f[i]);
        lo[i] = __float2bfloat16(f[i] - __bfloat162float(h[i]));
    }
    uint2 uh, ul;
    uh.x = pack_bf16x2(h[0], h[1]);  uh.y = pack_bf16x2(h[2], h[3]);
    ul.x = pack_bf16x2(lo[0], lo[1]); ul.y = pack_bf16x2(lo[2], lo[3]);
    int t = w >> 6, rl = w & 63, d0 = lane * 4;
    uint32_t off = (uint32_t)rl * 256 + ((((d0 >> 3) ^ (rl & 7)) & 15) << 4) + ((d0 & 7) << 1);
    unsigned char* base = g_x + (size_t)t * 32768;
    *(uint2*)(base + off)         = uh;
    *(uint2*)(base + 16384 + off) = ul;
}

// ---------------------------------------------------------------------------
__device__ __forceinline__ void write_mu(int k, int d, float nv) {
    __nv_bfloat16 h = __float2bfloat16(nv);
    __nv_bfloat16 l = __float2bfloat16(nv - __bfloat162float(h));
    uint32_t off = (uint32_t)k * 256 + ((((d >> 3) ^ (k & 7)) & 15) << 4) + ((d & 7) << 1);
    *(__nv_bfloat16*)(g_mu + off)         = h;
    *(__nv_bfloat16*)(g_mu + 16384 + off) = l;
}

__global__ void init_mu_kernel(const float* __restrict__ init) {
    int k = blockIdx.x, d = threadIdx.x;
    float v = init[k * D + d];
    __shared__ float sred[4];
    float ss = v * v;
    #pragma unroll
    for (int o = 16; o > 0; o >>= 1) ss += __shfl_xor_sync(0xffffffffu, ss, o);
    if ((d & 31) == 0) sred[d >> 5] = ss;
    __syncthreads();
    float tot = sred[0] + sred[1] + sred[2] + sred[3];
    write_mu(k, d, v / (sqrtf(tot) + EPSn));
}

// ---------------------------------------------------------------------------
// Fused: reduce 296 partials + normalize + write mu. grid=K, block=256.
__global__ void update_kernel(int last, float* __restrict__ mu_out) {
    int k = blockIdx.x, t = threadIdx.x;
    int d = t & 127, half = t >> 7;
    const float* pm = g_pmean + (size_t)k * D + d + (size_t)half * 148 * K * D;
    float s = 0.0f;
    #pragma unroll 4
    for (int j = 0; j < 148; j++)
        s += pm[(size_t)j * (K * D)];
    __shared__ float ssum[256];
    __shared__ float scb[8];
    __shared__ float sred[8];
    ssum[t] = s;
    float c = 0.0f;
    for (int b = t; b < NBLK; b += 256) c += g_pcnt[b * K + k];
    #pragma unroll
    for (int o = 16; o > 0; o >>= 1) c += __shfl_xor_sync(0xffffffffu, c, o);
    if ((t & 31) == 0) scb[t >> 5] = c;
    __syncthreads();
    float cs = scb[0] + scb[1] + scb[2] + scb[3] + scb[4] + scb[5] + scb[6] + scb[7];
    float v = (t < 128) ? (ssum[t] + ssum[t + 128]) / cs : 0.0f;
    float ss2 = v * v;
    #pragma unroll
    for (int o = 16; o > 0; o >>= 1) ss2 += __shfl_xor_sync(0xffffffffu, ss2, o);
    __syncthreads();
    if ((t & 31) == 0) sred[t >> 5] = ss2;
    __syncthreads();
    float tot = sred[0] + sred[1] + sred[2] + sred[3];
    if (t < 128) {
        if (last) mu_out[k * D + d] = v;
        else      write_mu(k, d, v / (sqrtf(tot) + EPSn));
    }
}

// ---------------------------------------------------------------------------
// 256 threads (8 warps), 2 CTAs/SM, TILE=64.
// GEMM1: warp w -> rows (w&3)*16, clusters (w>>2)*32 (half).
// GEMM2: warp w -> kc (w&3)*16, d half (w>>2)*64.
template<bool LAST>
__global__ void __launch_bounds__(256, 2) iter_kernel(float* __restrict__ r_out,
                                                      int N, int nT) {
    extern __shared__ unsigned char sm[];
    int tid = threadIdx.x, w = tid >> 5, lane = tid & 31;
    int bid = blockIdx.x;
    int t0 = (int)((long long)bid * nT / gridDim.x);
    int t1 = (int)((long long)(bid + 1) * nT / gridDim.x);
    float* gp = g_pmean + (size_t)bid * K * D;
    if (t0 >= t1) {
        for (int i = tid; i < K * D; i += 256) gp[i] = 0.0f;
        if (tid < K) g_pcnt[bid * K + tid] = 0.0f;
        return;
    }
    uint32_t sb = smem_u32(sm);
    uint32_t sMuH = sb + OFF_MU;
    uint32_t sR   = sb + OFF_R;

    // stage Mu (32K) + X(t0) (32K)
    #pragma unroll
    for (int j = 0; j < 8; j++)
        cp16(sMuH + (tid + 256 * j) * 16, g_mu + (tid + 256 * j) * 16);
    {
        const unsigned char* gx = g_x + (size_t)t0 * 32768;
        #pragma unroll
        for (int j = 0; j < 8; j++)
            cp16(sb + OFF_X + (tid + 256 * j) * 16, gx + (tid + 256 * j) * 16);
    }
    CP_COMMIT(); CP_WAIT0();
    __syncthreads();

    float C2[8][4];
    #pragma unroll
    for (int f = 0; f < 8; f++)
        #pragma unroll
        for (int q = 0; q < 4; q++) C2[f][q] = 0.0f;
    float cacc[8];
    #pragma unroll
    for (int j = 0; j < 8; j++) cacc[j] = 0.0f;

    int rs  = (w & 3) * 16;                 // GEMM1 row strip
    int ch  = w >> 2;                       // GEMM1 cluster half (0/1)
    int kc0 = (w & 3) * 16;                 // GEMM2 cluster strip
    int dbase = (w >> 2) * 64;              // GEMM2 d half
    int g = lane >> 2, j2 = lane & 3;

    for (int t = t0; t < t1; t++) {
        int buf = (t - t0) & 1;
        uint32_t sX = sb + OFF_X + buf * 32768;            // Xh; Xl at +16384
        float* sSum = (float*)(sm + OFF_X + (buf ^ 1) * 32768);  // dead buffer

        // ---- GEMM1: C1[16 rows x 32 kc] = X . Mu^T (3-term split) ----
        float C1[4][4];
        #pragma unroll
        for (int f = 0; f < 4; f++)
            #pragma unroll
            for (int q = 0; q < 4; q++) C1[f][q] = 0.0f;
        #pragma unroll
        for (int ks = 0; ks < 8; ks++) {
            uint32_t ah[4], al[4];
            int ar = rs + (lane & 15);
            int ac = ks * 16 + ((lane >> 4) << 3);
            uint32_t aaddr = sX + (uint32_t)ar * 256 + ((((ac >> 3) ^ (ar & 7)) & 15) << 4);
            ldsm_x4(ah, aaddr);
            ldsm_x4(al, aaddr + 16384);
            #pragma unroll
            for (int fp = 0; fp < 2; fp++) {
                int brow = ch * 32 + 16 * fp + ((lane >> 4) << 3) + (lane & 7);
                int bc = ks * 16 + (((lane >> 3) & 1) << 3);
                uint32_t baddr = sMuH + (uint32_t)brow * 256 + ((((bc >> 3) ^ (brow & 7)) & 15) << 4);
                uint32_t bh4[4], bl4[4];
                ldsm_x4(bh4, baddr);
                ldsm_x4(bl4, baddr + 16384);
                mma_bf16(C1[2*fp],   ah, bh4);
                mma_bf16(C1[2*fp],   al, bh4);
                mma_bf16(C1[2*fp],   ah, bl4);
                mma_bf16(C1[2*fp+1], ah, bh4 + 2);
                mma_bf16(C1[2*fp+1], al, bh4 + 2);
                mma_bf16(C1[2*fp+1], ah, bl4 + 2);
            }
        }

        // ---- softmax part 1: exp + per-half sums ----
        float s0 = 0.0f, s1 = 0.0f;
        #pragma unroll
        for (int f = 0; f < 4; f++) {
            #pragma unroll
            for (int q = 0; q < 4; q++) C1[f][q] = __expf(TEMP * C1[f][q]);
            s0 += C1[f][0] + C1[f][1];
            s1 += C1[f][2] + C1[f][3];
        }
        s0 += __shfl_xor_sync(0xffffffffu, s0, 1); s0 += __shfl_xor_sync(0xffffffffu, s0, 2);
        s1 += __shfl_xor_sync(0xffffffffu, s1, 1); s1 += __shfl_xor_sync(0xffffffffu, s1, 2);
        int row0 = rs + g, row1 = row0 + 8;
        sSum[ch * 64 + row0] = s0;
        sSum[ch * 64 + row1] = s1;
        __syncthreads();

        // ---- softmax part 2: scale, write R, cacc ----
        int grow0 = t * TILE + row0;
        int grow1 = t * TILE + row1;
        float inv0 = (grow0 < N) ? 1.0f / (sSum[row0] + sSum[64 + row0]) : 0.0f;
        float inv1 = (grow1 < N) ? 1.0f / (sSum[row1] + sSum[64 + row1]) : 0.0f;
        #pragma unroll
        for (int f = 0; f < 4; f++) {
            float r0a = C1[f][0] * inv0, r0b = C1[f][1] * inv0;
            float r1a = C1[f][2] * inv1, r1b = C1[f][3] * inv1;
            cacc[2*f]   += r0a + r1a;
            cacc[2*f+1] += r0b + r1b;
            int fg = ch * 4 + f;               // global n8 block (0..7)
            int kc = 8 * fg + 2 * j2;
            {
                __nv_bfloat16 ha = __float2bfloat16(r0a), hb = __float2bfloat16(r0b);
                __nv_bfloat16 la = __float2bfloat16(r0a - __bfloat162float(ha));
                __nv_bfloat16 lb = __float2bfloat16(r0b - __bfloat162float(hb));
                uint32_t off = (uint32_t)row0 * 128 + (((fg ^ (row0 & 7)) & 7) << 4) + (j2 << 2);
                *(uint32_t*)(sm + OFF_R + off)        = pack_bf16x2(ha, hb);
                *(uint32_t*)(sm + OFF_R + 8192 + off) = pack_bf16x2(la, lb);
            }
            {
                __nv_bfloat16 ha = __float2bfloat16(r1a), hb = __float2bfloat16(r1b);
                __nv_bfloat16 la = __float2bfloat16(r1a - __bfloat162float(ha));
                __nv_bfloat16 lb = __float2bfloat16(r1b - __bfloat162float(hb));
                uint32_t off = (uint32_t)row1 * 128 + (((fg ^ (row1 & 7)) & 7) << 4) + (j2 << 2);
                *(uint32_t*)(sm + OFF_R + off)        = pack_bf16x2(ha, hb);
                *(uint32_t*)(sm + OFF_R + 8192 + off) = pack_bf16x2(la, lb);
            }
            if (LAST) {
                if (grow0 < N) *(float2*)(r_out + (size_t)grow0 * K + kc) = make_float2(r0a, r0b);
                if (grow1 < N) *(float2*)(r_out + (size_t)grow1 * K + kc) = make_float2(r1a, r1b);
            }
        }
        __syncthreads();

        // ---- prefetch next tile into buf^1 (sSum consumed) ----
        if (t + 1 < t1) {
            const unsigned char* gx = g_x + (size_t)(t + 1) * 32768;
            uint32_t dst = sb + OFF_X + (buf ^ 1) * 32768;
            #pragma unroll
            for (int j = 0; j < 8; j++)
                cp16(dst + (tid + 256 * j) * 16, gx + (tid + 256 * j) * 16);
        }
        CP_COMMIT();

        // ---- GEMM2: C2[16 kc x 64 d] += R^T . X (3-term split), 4 ks ----
        #pragma unroll
        for (int ks = 0; ks < 4; ks++) {
            int row0k = ks * 16;
            uint32_t ah[4], al[4];
            int arm = row0k + (lane & 7) + ((lane >> 4) << 3);
            int acm = kc0 + ((lane >> 3) & 1) * 8;
            uint32_t aaddr = sR + (uint32_t)arm * 128 + ((((acm >> 3) ^ (arm & 7)) & 7) << 4);
            ldsm_x4t(ah, aaddr);
            ldsm_x4t(al, aaddr + 8192);
            #pragma unroll
            for (int fp = 0; fp < 4; fp++) {
                int brm = row0k + (((lane >> 3) & 1) << 3) + (lane & 7);
                int d0c = dbase + 16 * fp + ((lane >> 4) << 3);
                uint32_t baddr = sX + (uint32_t)brm * 256 + ((((d0c >> 3) ^ (brm & 7)) & 15) << 4);
                uint32_t bh4[4], bl4[4];
                ldsm_x4t(bh4, baddr);
                ldsm_x4t(bl4, baddr + 16384);
                mma_bf16(C2[2*fp],   ah, bh4);
                mma_bf16(C2[2*fp],   al, bh4);
                mma_bf16(C2[2*fp],   ah, bl4);
                mma_bf16(C2[2*fp+1], ah, bh4 + 2);
                mma_bf16(C2[2*fp+1], al, bh4 + 2);
                mma_bf16(C2[2*fp+1], ah, bl4 + 2);
            }
        }
        CP_WAIT0();
        __syncthreads();
    }

    // ---- counts: scnt in dead X region (after sync above) ----
    float* scnt = (float*)(sm + OFF_X);
    #pragma unroll
    for (int j = 0; j < 8; j++) {
        cacc[j] += __shfl_xor_sync(0xffffffffu, cacc[j], 4);
        cacc[j] += __shfl_xor_sync(0xffffffffu, cacc[j], 8);
        cacc[j] += __shfl_xor_sync(0xffffffffu, cacc[j], 16);
    }
    __syncthreads();   // ensure all GEMM2 reads of X done before scnt overwrite
    if (lane < 4) {
        #pragma unroll
        for (int f = 0; f < 4; f++) {
            scnt[w * 32 + 8 * f + 2 * lane]     = cacc[2*f];
            scnt[w * 32 + 8 * f + 2 * lane + 1] = cacc[2*f+1];
        }
    }
    __syncthreads();
    if (tid < K) {
        int chh = tid >> 5, cc = tid & 31;
        float c = scnt[(chh*4+0)*32 + cc] + scnt[(chh*4+1)*32 + cc]
                + scnt[(chh*4+2)*32 + cc] + scnt[(chh*4+3)*32 + cc];
        g_pcnt[bid * K + tid] = c;
    }
    // ---- mean partials ----
    #pragma unroll
    for (int f = 0; f < 8; f++) {
        int d0 = dbase + 8 * f + 2 * j2;
        *(float2*)(gp + (kc0 + g) * D + d0)     = make_float2(C2[f][0], C2[f][1]);
        *(float2*)(gp + (kc0 + g + 8) * D + d0) = make_float2(C2[f][2], C2[f][3]);
    }
}

// ---------------------------------------------------------------------------
extern "C" void kernel_launch(void* const* d_in, const int* in_sizes, int n_in,
                              void* d_out, int out_size) {
    const float* embeds = (const float*)d_in[0];
    const float* init   = (const float*)d_in[1];
    int N = in_sizes[0] / D;
    int nT = (N + TILE - 1) / TILE;
    if (nT > NT_MAX) nT = NT_MAX;
    float* out_mu = (float*)d_out;
    float* out_r  = (float*)d_out + K * D;

    cudaFuncSetAttribute(iter_kernel<false>, cudaFuncAttributeMaxDynamicSharedMemorySize, SMEM_TOTAL);
    cudaFuncSetAttribute(iter_kernel<true>,  cudaFuncAttributeMaxDynamicSharedMemorySize, SMEM_TOTAL);

    int rowsPad = nT * TILE;
    prep_kernel<<<(rowsPad + 7) / 8, 256>>>(embeds, N, rowsPad);
    init_mu_kernel<<<K, 128>>>(init);

    for (int it = 0; it < ITERS; it++) {
        int last = (it == ITERS - 1);
        if (last) iter_kernel<true><<<NBLK, 256, SMEM_TOTAL>>>(out_r, N, nT);
        else      iter_kernel<false><<<NBLK, 256, SMEM_TOTAL>>>(nullptr, N, nT);
        update_kernel<<<K, 256>>>(last, out_mu);
    }
}

// round 11
// speedup vs baseline: 1.1479x; 1.1479x over previous
#include <cuda_runtime.h>
#include <cuda_bf16.h>
#include <cstdint>

#define D 128
#define K 64
#define TILE 128
#define NT_MAX 1563
#define NB 148
#define TEMP 30.0f
#define EPSn 1e-6f
#define ITERS 11

// smem byte offsets
#define OFF_MU 0                 // MuH 16KB | MuL 16KB
#define OFF_X  32768             // buf0: Xh 32K | Xl 32K ; buf1 at +65536
#define OFF_R  163840            // Rh 16K | Rl 16K
#define OFF_CNT 196608           // 8*64 floats
#define SMEM_TOTAL (OFF_CNT + 2048)

__device__ __align__(16) unsigned char g_x[(size_t)NT_MAX * 65536]; // per tile: Xh 32K | Xl 32K, swizzled
__device__ __align__(16) unsigned char g_mu[32768];                 // MuH 16K | MuL 16K, swizzled
__device__ float g_mean[K * D];                                     // atomic accumulator
__device__ float g_pcnt[NB * K];

__device__ __forceinline__ uint32_t smem_u32(const void* p) {
    uint32_t a;
    asm("{ .reg .u64 t; cvta.to.shared.u64 t, %1; cvt.u32.u64 %0, t; }" : "=r"(a) : "l"(p));
    return a;
}
__device__ __forceinline__ void ldsm_x4(uint32_t* r, uint32_t a) {
    asm volatile("ldmatrix.sync.aligned.m8n8.x4.shared.b16 {%0,%1,%2,%3}, [%4];"
        : "=r"(r[0]), "=r"(r[1]), "=r"(r[2]), "=r"(r[3]) : "r"(a));
}
__device__ __forceinline__ void ldsm_x4t(uint32_t* r, uint32_t a) {
    asm volatile("ldmatrix.sync.aligned.m8n8.x4.trans.shared.b16 {%0,%1,%2,%3}, [%4];"
        : "=r"(r[0]), "=r"(r[1]), "=r"(r[2]), "=r"(r[3]) : "r"(a));
}
__device__ __forceinline__ void mma_bf16(float* c, const uint32_t* a, const uint32_t* b) {
    asm volatile("mma.sync.aligned.m16n8k16.row.col.f32.bf16.bf16.f32 "
        "{%0,%1,%2,%3}, {%4,%5,%6,%7}, {%8,%9}, {%0,%1,%2,%3};"
        : "+f"(c[0]), "+f"(c[1]), "+f"(c[2]), "+f"(c[3])
        : "r"(a[0]), "r"(a[1]), "r"(a[2]), "r"(a[3]), "r"(b[0]), "r"(b[1]));
}
__device__ __forceinline__ void cp16(uint32_t dst, const void* src) {
    asm volatile("cp.async.cg.shared.global [%0], [%1], 16;" :: "r"(dst), "l"(src) : "memory");
}
#define CP_COMMIT() asm volatile("cp.async.commit_group;" ::: "memory")
#define CP_WAIT0()  asm volatile("cp.async.wait_group 0;" ::: "memory")

__device__ __forceinline__ uint32_t pack_bf16x2(__nv_bfloat16 a, __nv_bfloat16 b) {
    __nv_bfloat162 v(a, b);
    return *(uint32_t*)&v;
}

// ---------------------------------------------------------------------------
__global__ void prep_kernel(const float* __restrict__ x, int N, int rowsPad) {
    int w = (blockIdx.x * blockDim.x + threadIdx.x) >> 5;
    int lane = threadIdx.x & 31;
    if (w >= rowsPad) return;
    float4 v = make_float4(0.f, 0.f, 0.f, 0.f);
    if (w < N) {
        v = ((const float4*)(x + (size_t)w * D))[lane];
        float ss = v.x*v.x + v.y*v.y + v.z*v.z + v.w*v.w;
        #pragma unroll
        for (int o = 16; o > 0; o >>= 1) ss += __shfl_xor_sync(0xffffffffu, ss, o);
        float inv = 1.0f / (sqrtf(ss) + EPSn);
        v.x *= inv; v.y *= inv; v.z *= inv; v.w *= inv;
    }
    float f[4] = {v.x, v.y, v.z, v.w};
    __nv_bfloat16 h[4], lo[4];
    #pragma unroll
    for (int i = 0; i < 4; i++) {
        h[i]  = __float2bfloat16(f[i]);
        lo[i] = __float2bfloat16(f[i] - __bfloat162float(h[i]));
    }
    uint2 uh, ul;
    uh.x = pack_bf16x2(h[0], h[1]);  uh.y = pack_bf16x2(h[2], h[3]);
    ul.x = pack_bf16x2(lo[0], lo[1]); ul.y = pack_bf16x2(lo[2], lo[3]);
    int t = w >> 7, rl = w & 127, d0 = lane * 4;
    uint32_t off = (uint32_t)rl * 256 + ((((d0 >> 3) ^ (rl & 7)) & 15) << 4) + ((d0 & 7) << 1);
    unsigned char* base = g_x + (size_t)t * 65536;
    *(uint2*)(base + off)         = uh;
    *(uint2*)(base + 32768 + off) = ul;
}

// ---------------------------------------------------------------------------
__device__ __forceinline__ void write_mu(int k, int d, float nv) {
    __nv_bfloat16 h = __float2bfloat16(nv);
    __nv_bfloat16 l = __float2bfloat16(nv - __bfloat162float(h));
    uint32_t off = (uint32_t)k * 256 + ((((d >> 3) ^ (k & 7)) & 15) << 4) + ((d & 7) << 1);
    *(__nv_bfloat16*)(g_mu + off)         = h;
    *(__nv_bfloat16*)(g_mu + 16384 + off) = l;
}

__global__ void init_mu_kernel(const float* __restrict__ init) {
    int k = blockIdx.x, d = threadIdx.x;
    float v = init[k * D + d];
    __shared__ float sred[4];
    float ss = v * v;
    #pragma unroll
    for (int o = 16; o > 0; o >>= 1) ss += __shfl_xor_sync(0xffffffffu, ss, o);
    if ((d & 31) == 0) sred[d >> 5] = ss;
    __syncthreads();
    float tot = sred[0] + sred[1] + sred[2] + sred[3];
    write_mu(k, d, v / (sqrtf(tot) + EPSn));
    g_mean[k * D + d] = 0.0f;      // seed accumulator for iteration 0
}

// ---------------------------------------------------------------------------
// grid=K, block=128: parallel cnt reduce, read+zero g_mean, normalize, write mu.
__global__ void update_kernel(int last, float* __restrict__ mu_out) {
    int k = blockIdx.x, d = threadIdx.x;
    __shared__ float swred[4];
    __shared__ float sred[4];
    float c = 0.0f;
    for (int b = d; b < NB; b += 128) c += g_pcnt[b * K + k];
    #pragma unroll
    for (int o = 16; o > 0; o >>= 1) c += __shfl_xor_sync(0xffffffffu, c, o);
    if ((d & 31) == 0) swred[d >> 5] = c;
    __syncthreads();
    float cs = swred[0] + swred[1] + swred[2] + swred[3];
    float v = g_mean[k * D + d] / cs;
    g_mean[k * D + d] = 0.0f;      // reset for next iteration's atomics
    float ss = v * v;
    #pragma unroll
    for (int o = 16; o > 0; o >>= 1) ss += __shfl_xor_sync(0xffffffffu, ss, o);
    if ((d & 31) == 0) sred[d >> 5] = ss;
    __syncthreads();
    float tot = sred[0] + sred[1] + sred[2] + sred[3];
    if (last) mu_out[k * D + d] = v;
    else      write_mu(k, d, v / (sqrtf(tot) + EPSn));
}

// ---------------------------------------------------------------------------
template<bool LAST>
__global__ void __launch_bounds__(256, 1) iter_kernel(float* __restrict__ r_out,
                                                      int N, int nT) {
    extern __shared__ unsigned char sm[];
    int tid = threadIdx.x, w = tid >> 5, lane = tid & 31;
    int bid = blockIdx.x;
    int t0 = (int)((long long)bid * nT / gridDim.x);
    int t1 = (int)((long long)(bid + 1) * nT / gridDim.x);
    if (t0 >= t1) {
        if (tid < K) g_pcnt[bid * K + tid] = 0.0f;
        return;
    }
    uint32_t sb = smem_u32(sm);
    uint32_t sMuH = sb + OFF_MU;
    uint32_t sR   = sb + OFF_R;
    float* scnt = (float*)(sm + OFF_CNT);

    // stage Mu (32KB) + X(t0) (64KB)
    #pragma unroll
    for (int j = 0; j < 8; j++)
        cp16(sMuH + (tid + 256 * j) * 16, g_mu + (tid + 256 * j) * 16);
    {
        const unsigned char* gx = g_x + (size_t)t0 * 65536;
        #pragma unroll
        for (int j = 0; j < 16; j++)
            cp16(sb + OFF_X + (tid + 256 * j) * 16, gx + (tid + 256 * j) * 16);
    }
    CP_COMMIT(); CP_WAIT0();
    __syncthreads();

    float C2[8][4];
    #pragma unroll
    for (int f = 0; f < 8; f++)
        #pragma unroll
        for (int q = 0; q < 4; q++) C2[f][q] = 0.0f;
    float cacc[16];
    #pragma unroll
    for (int j = 0; j < 16; j++) cacc[j] = 0.0f;

    int m0  = w * 16;                       // GEMM1 row strip
    int kc0 = (w & 3) * 16;                 // GEMM2 cluster strip
    int db  = (w >> 2) * 64;                // GEMM2 d half
    int g = lane >> 2, j2 = lane & 3;

    for (int t = t0; t < t1; t++) {
        int buf = (t - t0) & 1;
        uint32_t sX = sb + OFF_X + buf * 65536;       // Xh; Xl at +32768
        if (t + 1 < t1) {
            const unsigned char* gx = g_x + (size_t)(t + 1) * 65536;
            uint32_t dst = sb + OFF_X + (buf ^ 1) * 65536;
            #pragma unroll
            for (int j = 0; j < 16; j++)
                cp16(dst + (tid + 256 * j) * 16, gx + (tid + 256 * j) * 16);
        }
        CP_COMMIT();

        // ---- GEMM1: C1[16 rows x 64 kc] = X . Mu^T (3-term split) ----
        float C1[8][4];
        #pragma unroll
        for (int f = 0; f < 8; f++)
            #pragma unroll
            for (int q = 0; q < 4; q++) C1[f][q] = 0.0f;
        #pragma unroll
        for (int ks = 0; ks < 8; ks++) {
            uint32_t ah[4], al[4];
            int ar = m0 + (lane & 15);
            int ac = ks * 16 + ((lane >> 4) << 3);
            uint32_t aaddr = sX + (uint32_t)ar * 256 + ((((ac >> 3) ^ (ar & 7)) & 15) << 4);
            ldsm_x4(ah, aaddr);
            ldsm_x4(al, aaddr + 32768);
            #pragma unroll
            for (int fp = 0; fp < 4; fp++) {
                int brow = 16 * fp + ((lane >> 4) << 3) + (lane & 7);
                int bc = ks * 16 + (((lane >> 3) & 1) << 3);
                uint32_t baddr = sMuH + (uint32_t)brow * 256 + ((((bc >> 3) ^ (brow & 7)) & 15) << 4);
                uint32_t bh4[4], bl4[4];
                ldsm_x4(bh4, baddr);
                ldsm_x4(bl4, baddr + 16384);
                mma_bf16(C1[2*fp],   ah, bh4);
                mma_bf16(C1[2*fp],   al, bh4);
                mma_bf16(C1[2*fp],   ah, bl4);
                mma_bf16(C1[2*fp+1], ah, bh4 + 2);
                mma_bf16(C1[2*fp+1], al, bh4 + 2);
                mma_bf16(C1[2*fp+1], ah, bl4 + 2);
            }
        }

        // ---- softmax (max-free; |logit| <= ~30) ----
        int grow0 = t * TILE + m0 + g;
        int grow1 = grow0 + 8;
        float s0 = 0.0f, s1 = 0.0f;
        #pragma unroll
        for (int f = 0; f < 8; f++) {
            #pragma unroll
            for (int q = 0; q < 4; q++) C1[f][q] = __expf(TEMP * C1[f][q]);
            s0 += C1[f][0] + C1[f][1];
            s1 += C1[f][2] + C1[f][3];
        }
        s0 += __shfl_xor_sync(0xffffffffu, s0, 1); s0 += __shfl_xor_sync(0xffffffffu, s0, 2);
        s1 += __shfl_xor_sync(0xffffffffu, s1, 1); s1 += __shfl_xor_sync(0xffffffffu, s1, 2);
        float inv0 = (grow0 < N) ? 1.0f / s0 : 0.0f;
        float inv1 = (grow1 < N) ? 1.0f / s1 : 0.0f;
        int row0 = m0 + g, row1 = row0 + 8;
        #pragma unroll
        for (int f = 0; f < 8; f++) {
            float r0a = C1[f][0] * inv0, r0b = C1[f][1] * inv0;
            float r1a = C1[f][2] * inv1, r1b = C1[f][3] * inv1;
            cacc[2*f]   += r0a + r1a;
            cacc[2*f+1] += r0b + r1b;
            int kc = 8 * f + 2 * j2;
            {
                __nv_bfloat16 ha = __float2bfloat16(r0a), hb = __float2bfloat16(r0b);
                __nv_bfloat16 la = __float2bfloat16(r0a - __bfloat162float(ha));
                __nv_bfloat16 lb = __float2bfloat16(r0b - __bfloat162float(hb));
                uint32_t off = (uint32_t)row0 * 128 + (((f ^ (row0 & 7)) & 7) << 4) + (j2 << 2);
                *(uint32_t*)(sm + OFF_R + off)         = pack_bf16x2(ha, hb);
                *(uint32_t*)(sm + OFF_R + 16384 + off) = pack_bf16x2(la, lb);
            }
            {
                __nv_bfloat16 ha = __float2bfloat16(r1a), hb = __float2bfloat16(r1b);
                __nv_bfloat16 la = __float2bfloat16(r1a - __bfloat162float(ha));
                __nv_bfloat16 lb = __float2bfloat16(r1b - __bfloat162float(hb));
                uint32_t off = (uint32_t)row1 * 128 + (((f ^ (row1 & 7)) & 7) << 4) + (j2 << 2);
                *(uint32_t*)(sm + OFF_R + off)         = pack_bf16x2(ha, hb);
                *(uint32_t*)(sm + OFF_R + 16384 + off) = pack_bf16x2(la, lb);
            }
            if (LAST) {
                if (grow0 < N) *(float2*)(r_out + (size_t)grow0 * K + kc) = make_float2(r0a, r0b);
                if (grow1 < N) *(float2*)(r_out + (size_t)grow1 * K + kc) = make_float2(r1a, r1b);
            }
        }
        __syncthreads();

        // ---- GEMM2: C2[16 kc x 64 d] += R^T . X (3-term split) ----
        #pragma unroll
        for (int ks = 0; ks < 8; ks++) {
            int row0k = ks * 16;
            uint32_t ah[4], al[4];
            int arm = row0k + (lane & 7) + ((lane >> 4) << 3);
            int acm = kc0 + ((lane >> 3) & 1) * 8;
            uint32_t aaddr = sR + (uint32_t)arm * 128 + ((((acm >> 3) ^ (arm & 7)) & 7) << 4);
            ldsm_x4t(ah, aaddr);
            ldsm_x4t(al, aaddr + 16384);
            #pragma unroll
            for (int fp = 0; fp < 4; fp++) {
                int brm = row0k + (((lane >> 3) & 1) << 3) + (lane & 7);
                int d0c = db + 16 * fp + ((lane >> 4) << 3);
                uint32_t baddr = sX + (uint32_t)brm * 256 + ((((d0c >> 3) ^ (brm & 7)) & 15) << 4);
                uint32_t bh4[4], bl4[4];
                ldsm_x4t(bh4, baddr);
                ldsm_x4t(bl4, baddr + 32768);
                mma_bf16(C2[2*fp],   ah, bh4);
                mma_bf16(C2[2*fp],   al, bh4);
                mma_bf16(C2[2*fp],   ah, bl4);
                mma_bf16(C2[2*fp+1], ah, bh4 + 2);
                mma_bf16(C2[2*fp+1], al, bh4 + 2);
                mma_bf16(C2[2*fp+1], ah, bl4 + 2);
            }
        }
        CP_WAIT0();
        __syncthreads();
    }

    // ---- epilogue: counts ----
    #pragma unroll
    for (int j = 0; j < 16; j++) {
        cacc[j] += __shfl_xor_sync(0xffffffffu, cacc[j], 4);
        cacc[j] += __shfl_xor_sync(0xffffffffu, cacc[j], 8);
        cacc[j] += __shfl_xor_sync(0xffffffffu, cacc[j], 16);
    }
    if (lane < 4) {
        #pragma unroll
        for (int f = 0; f < 8; f++) {
            scnt[w * 64 + 8 * f + 2 * lane]     = cacc[2*f];
            scnt[w * 64 + 8 * f + 2 * lane + 1] = cacc[2*f+1];
        }
    }
    __syncthreads();
    if (tid < K) {
        float c = 0.0f;
        #pragma unroll
        for (int ww = 0; ww < 8; ww++) c += scnt[ww * 64 + tid];
        g_pcnt[bid * K + tid] = c;
    }
    // ---- epilogue: mean via atomics (no partial buffers, no reduce kernel) ----
    #pragma unroll
    for (int f = 0; f < 8; f++) {
        int d0 = db + 8 * f + 2 * j2;
        atomicAdd(&g_mean[(kc0 + g) * D + d0],     C2[f][0]);
        atomicAdd(&g_mean[(kc0 + g) * D + d0 + 1], C2[f][1]);
        atomicAdd(&g_mean[(kc0 + g + 8) * D + d0],     C2[f][2]);
        atomicAdd(&g_mean[(kc0 + g + 8) * D + d0 + 1], C2[f][3]);
    }
}

// ---------------------------------------------------------------------------
extern "C" void kernel_launch(void* const* d_in, const int* in_sizes, int n_in,
                              void* d_out, int out_size) {
    const float* embeds = (const float*)d_in[0];
    const float* init   = (const float*)d_in[1];
    int N = in_sizes[0] / D;
    int nT = (N + TILE - 1) / TILE;
    if (nT > NT_MAX) nT = NT_MAX;
    float* out_mu = (float*)d_out;
    float* out_r  = (float*)d_out + K * D;

    cudaFuncSetAttribute(iter_kernel<false>, cudaFuncAttributeMaxDynamicSharedMemorySize, SMEM_TOTAL);
    cudaFuncSetAttribute(iter_kernel<true>,  cudaFuncAttributeMaxDynamicSharedMemorySize, SMEM_TOTAL);

    int rowsPad = nT * TILE;
    prep_kernel<<<(rowsPad + 7) / 8, 256>>>(embeds, N, rowsPad);
    init_mu_kernel<<<K, 128>>>(init);

    for (int it = 0; it < ITERS; it++) {
        int last = (it == ITERS - 1);
        if (last) iter_kernel<true><<<NB, 256, SMEM_TOTAL>>>(out_r, N, nT);
        else      iter_kernel<false><<<NB, 256, SMEM_TOTAL>>>(nullptr, N, nT);
        update_kernel<<<K, 128>>>(last, out_mu);
    }
}

// round 13
// speedup vs baseline: 1.2250x; 1.0672x over previous
#include <cuda_runtime.h>
#include <cuda_bf16.h>
#include <cstdint>

#define D 128
#define K 64
#define TILE 128
#define NT_MAX 1563
#define NB 148
#define TEMP 30.0f
#define EPSn 1e-6f
#define ITERS 11

// smem byte offsets
#define OFF_MU 0                 // MuH 16KB | MuL 16KB
#define OFF_X  32768             // buf0: Xh 32K | Xl 32K ; buf1 at +65536
#define OFF_R  163840            // Rh 16K (128 rows x 64 kc x 2B)
#define OFF_CNT 180224           // scratch: snorm/scnt (256+ floats)
#define SMEM_TOTAL (OFF_CNT + 2048)

__device__ __align__(16) unsigned char g_x[(size_t)NT_MAX * 65536]; // per tile: Xh 32K | Xl 32K, swizzled
__device__ float g_mu_raw[(ITERS + 1) * K * D];  // slots 1..11 atomically accumulated
__device__ float g_cc[(ITERS + 1) * K];

__device__ __forceinline__ uint32_t smem_u32(const void* p) {
    uint32_t a;
    asm("{ .reg .u64 t; cvta.to.shared.u64 t, %1; cvt.u32.u64 %0, t; }" : "=r"(a) : "l"(p));
    return a;
}
__device__ __forceinline__ void ldsm_x4(uint32_t* r, uint32_t a) {
    asm volatile("ldmatrix.sync.aligned.m8n8.x4.shared.b16 {%0,%1,%2,%3}, [%4];"
        : "=r"(r[0]), "=r"(r[1]), "=r"(r[2]), "=r"(r[3]) : "r"(a));
}
__device__ __forceinline__ void ldsm_x4t(uint32_t* r, uint32_t a) {
    asm volatile("ldmatrix.sync.aligned.m8n8.x4.trans.shared.b16 {%0,%1,%2,%3}, [%4];"
        : "=r"(r[0]), "=r"(r[1]), "=r"(r[2]), "=r"(r[3]) : "r"(a));
}
__device__ __forceinline__ void mma_bf16(float* c, const uint32_t* a, const uint32_t* b) {
    asm volatile("mma.sync.aligned.m16n8k16.row.col.f32.bf16.bf16.f32 "
        "{%0,%1,%2,%3}, {%4,%5,%6,%7}, {%8,%9}, {%0,%1,%2,%3};"
        : "+f"(c[0]), "+f"(c[1]), "+f"(c[2]), "+f"(c[3])
        : "r"(a[0]), "r"(a[1]), "r"(a[2]), "r"(a[3]), "r"(b[0]), "r"(b[1]));
}
__device__ __forceinline__ void cp16(uint32_t dst, const void* src) {
    asm volatile("cp.async.cg.shared.global [%0], [%1], 16;" :: "r"(dst), "l"(src) : "memory");
}
#define CP_COMMIT() asm volatile("cp.async.commit_group;" ::: "memory")
#define CP_WAIT0()  asm volatile("cp.async.wait_group 0;" ::: "memory")

__device__ __forceinline__ uint32_t pack_bf16x2(__nv_bfloat16 a, __nv_bfloat16 b) {
    __nv_bfloat162 v(a, b);
    return *(uint32_t*)&v;
}

// ---------------------------------------------------------------------------
__global__ void prep_kernel(const float* __restrict__ x, int N, int rowsPad) {
    int w = (blockIdx.x * blockDim.x + threadIdx.x) >> 5;
    int lane = threadIdx.x & 31;
    if (w >= rowsPad) return;
    float4 v = make_float4(0.f, 0.f, 0.f, 0.f);
    if (w < N) {
        v = ((const float4*)(x + (size_t)w * D))[lane];
        float ss = v.x*v.x + v.y*v.y + v.z*v.z + v.w*v.w;
        #pragma unroll
        for (int o = 16; o > 0; o >>= 1) ss += __shfl_xor_sync(0xffffffffu, ss, o);
        float inv = 1.0f / (sqrtf(ss) + EPSn);
        v.x *= inv; v.y *= inv; v.z *= inv; v.w *= inv;
    }
    float f[4] = {v.x, v.y, v.z, v.w};
    __nv_bfloat16 h[4], lo[4];
    #pragma unroll
    for (int i = 0; i < 4; i++) {
        h[i]  = __float2bfloat16(f[i]);
        lo[i] = __float2bfloat16(f[i] - __bfloat162float(h[i]));
    }
    uint2 uh, ul;
    uh.x = pack_bf16x2(h[0], h[1]);  uh.y = pack_bf16x2(h[2], h[3]);
    ul.x = pack_bf16x2(lo[0], lo[1]); ul.y = pack_bf16x2(lo[2], lo[3]);
    int t = w >> 7, rl = w & 127, d0 = lane * 4;
    uint32_t off = (uint32_t)rl * 256 + ((((d0 >> 3) ^ (rl & 7)) & 15) << 4) + ((d0 & 7) << 1);
    unsigned char* base = g_x + (size_t)t * 65536;
    *(uint2*)(base + off)         = uh;
    *(uint2*)(base + 32768 + off) = ul;
}

// ---------------------------------------------------------------------------
__global__ void zero_kernel() {
    int i = blockIdx.x * 512 + threadIdx.x;
    if (i < ITERS * K * D) g_mu_raw[K * D + i] = 0.0f;
    if (i < (ITERS + 1) * K) g_cc[i] = 0.0f;
}

__global__ void final_mu_kernel(float* __restrict__ mu_out) {
    int k = blockIdx.x, d = threadIdx.x;
    mu_out[k * D + d] = g_mu_raw[ITERS * K * D + k * D + d] / g_cc[ITERS * K + k];
}

// ---------------------------------------------------------------------------
template<bool LAST>
__global__ void __launch_bounds__(256, 1) iter_kernel(float* __restrict__ r_out,
                                                      const float* __restrict__ mu_init,
                                                      int N, int nT, int it) {
    extern __shared__ unsigned char sm[];
    int tid = threadIdx.x, w = tid >> 5, lane = tid & 31;
    int bid = blockIdx.x;
    int t0 = (int)((long long)bid * nT / gridDim.x);
    int t1 = (int)((long long)(bid + 1) * nT / gridDim.x);
    if (t0 >= t1) return;
    uint32_t sb = smem_u32(sm);
    uint32_t sMuH = sb + OFF_MU;
    uint32_t sR   = sb + OFF_R;

    // issue X(t0) load (64KB) first
    {
        const unsigned char* gx = g_x + (size_t)t0 * 65536;
        #pragma unroll
        for (int j = 0; j < 16; j++)
            cp16(sb + OFF_X + (tid + 256 * j) * 16, gx + (tid + 256 * j) * 16);
    }
    CP_COMMIT();

    // ---- fused mu update: v = raw(/cnt), normalize, split bf16 hi/lo -> sMu ----
    {
        int kk = tid & 63, dpart = tid >> 6;
        const float* msrc = (it == 0) ? mu_init : (g_mu_raw + (size_t)it * (K * D));
        float cinv = (it == 0) ? 1.0f : (1.0f / g_cc[it * K + kk]);
        const float* row = msrc + kk * D + dpart * 32;
        float v[32];
        float ss = 0.0f;
        #pragma unroll
        for (int j = 0; j < 32; j++) {
            float x = row[j] * cinv;
            v[j] = x;
            ss += x * x;
        }
        float* snorm = (float*)(sm + OFF_CNT);
        snorm[tid] = ss;
        __syncthreads();
        float tot = snorm[kk] + snorm[kk + 64] + snorm[kk + 128] + snorm[kk + 192];
        float inv = 1.0f / (sqrtf(tot) + EPSn);
        #pragma unroll
        for (int j = 0; j < 32; j += 2) {
            float n0 = v[j] * inv, n1 = v[j + 1] * inv;
            __nv_bfloat16 h0 = __float2bfloat16(n0), h1 = __float2bfloat16(n1);
            __nv_bfloat16 l0 = __float2bfloat16(n0 - __bfloat162float(h0));
            __nv_bfloat16 l1 = __float2bfloat16(n1 - __bfloat162float(h1));
            int d = dpart * 32 + j;
            uint32_t off = (uint32_t)kk * 256 + ((((d >> 3) ^ (kk & 7)) & 15) << 4) + ((d & 7) << 1);
            *(uint32_t*)(sm + OFF_MU + off)         = pack_bf16x2(h0, h1);
            *(uint32_t*)(sm + OFF_MU + 16384 + off) = pack_bf16x2(l0, l1);
        }
    }
    CP_WAIT0();
    __syncthreads();

    float C2[8][4];
    #pragma unroll
    for (int f = 0; f < 8; f++)
        #pragma unroll
        for (int q = 0; q < 4; q++) C2[f][q] = 0.0f;
    float cacc[16];
    #pragma unroll
    for (int j = 0; j < 16; j++) cacc[j] = 0.0f;

    int m0  = w * 16;                       // GEMM1 row strip
    int kc0 = (w & 3) * 16;                 // GEMM2 cluster strip
    int db  = (w >> 2) * 64;                // GEMM2 d half
    int g = lane >> 2, j2 = lane & 3;

    for (int t = t0; t < t1; t++) {
        int buf = (t - t0) & 1;
        uint32_t sX = sb + OFF_X + buf * 65536;       // Xh; Xl at +32768
        if (t + 1 < t1) {
            const unsigned char* gx = g_x + (size_t)(t + 1) * 65536;
            uint32_t dst = sb + OFF_X + (buf ^ 1) * 65536;
            #pragma unroll
            for (int j = 0; j < 16; j++)
                cp16(dst + (tid + 256 * j) * 16, gx + (tid + 256 * j) * 16);
        }
        CP_COMMIT();

        // ---- GEMM1: C1[16 rows x 64 kc] = X . Mu^T (3-term split) ----
        float C1[8][4];
        #pragma unroll
        for (int f = 0; f < 8; f++)
            #pragma unroll
            for (int q = 0; q < 4; q++) C1[f][q] = 0.0f;
        #pragma unroll
        for (int ks = 0; ks < 8; ks++) {
            uint32_t ah[4], al[4];
            int ar = m0 + (lane & 15);
            int ac = ks * 16 + ((lane >> 4) << 3);
            uint32_t aaddr = sX + (uint32_t)ar * 256 + ((((ac >> 3) ^ (ar & 7)) & 15) << 4);
            ldsm_x4(ah, aaddr);
            ldsm_x4(al, aaddr + 32768);
            #pragma unroll
            for (int fp = 0; fp < 4; fp++) {
                int brow = 16 * fp + ((lane >> 4) << 3) + (lane & 7);
                int bc = ks * 16 + (((lane >> 3) & 1) << 3);
                uint32_t baddr = sMuH + (uint32_t)brow * 256 + ((((bc >> 3) ^ (brow & 7)) & 15) << 4);
                uint32_t bh4[4], bl4[4];
                ldsm_x4(bh4, baddr);
                ldsm_x4(bl4, baddr + 16384);
                mma_bf16(C1[2*fp],   ah, bh4);
                mma_bf16(C1[2*fp],   al, bh4);
                mma_bf16(C1[2*fp],   ah, bl4);
                mma_bf16(C1[2*fp+1], ah, bh4 + 2);
                mma_bf16(C1[2*fp+1], al, bh4 + 2);
                mma_bf16(C1[2*fp+1], ah, bl4 + 2);
            }
        }

        // ---- softmax (max-free; |logit| <= ~30) ----
        int grow0 = t * TILE + m0 + g;
        int grow1 = grow0 + 8;
        float s0 = 0.0f, s1 = 0.0f;
        #pragma unroll
        for (int f = 0; f < 8; f++) {
            #pragma unroll
            for (int q = 0; q < 4; q++) C1[f][q] = __expf(TEMP * C1[f][q]);
            s0 += C1[f][0] + C1[f][1];
            s1 += C1[f][2] + C1[f][3];
        }
        s0 += __shfl_xor_sync(0xffffffffu, s0, 1); s0 += __shfl_xor_sync(0xffffffffu, s0, 2);
        s1 += __shfl_xor_sync(0xffffffffu, s1, 1); s1 += __shfl_xor_sync(0xffffffffu, s1, 2);
        float inv0 = (grow0 < N) ? 1.0f / s0 : 0.0f;
        float inv1 = (grow1 < N) ? 1.0f / s1 : 0.0f;
        int row0 = m0 + g, row1 = row0 + 8;
        #pragma unroll
        for (int f = 0; f < 8; f++) {
            float r0a = C1[f][0] * inv0, r0b = C1[f][1] * inv0;
            float r1a = C1[f][2] * inv1, r1b = C1[f][3] * inv1;
            cacc[2*f]   += r0a + r1a;
            cacc[2*f+1] += r0b + r1b;
            int kc = 8 * f + 2 * j2;
            {
                uint32_t off = (uint32_t)row0 * 128 + (((f ^ (row0 & 7)) & 7) << 4) + (j2 << 2);
                *(uint32_t*)(sm + OFF_R + off) =
                    pack_bf16x2(__float2bfloat16(r0a), __float2bfloat16(r0b));
            }
            {
                uint32_t off = (uint32_t)row1 * 128 + (((f ^ (row1 & 7)) & 7) << 4) + (j2 << 2);
                *(uint32_t*)(sm + OFF_R + off) =
                    pack_bf16x2(__float2bfloat16(r1a), __float2bfloat16(r1b));
            }
            if (LAST) {
                if (grow0 < N) *(float2*)(r_out + (size_t)grow0 * K + kc) = make_float2(r0a, r0b);
                if (grow1 < N) *(float2*)(r_out + (size_t)grow1 * K + kc) = make_float2(r1a, r1b);
            }
        }
        __syncthreads();

        // ---- GEMM2: C2[16 kc x 64 d] += Rh^T . (Xh + Xl) (2-term) ----
        #pragma unroll
        for (int ks = 0; ks < 8; ks++) {
            int row0k = ks * 16;
            uint32_t ah[4];
            int arm = row0k + (lane & 7) + ((lane >> 4) << 3);
            int acm = kc0 + ((lane >> 3) & 1) * 8;
            uint32_t aaddr = sR + (uint32_t)arm * 128 + ((((acm >> 3) ^ (arm & 7)) & 7) << 4);
            ldsm_x4t(ah, aaddr);
            #pragma unroll
            for (int fp = 0; fp < 4; fp++) {
                int brm = row0k + (((lane >> 3) & 1) << 3) + (lane & 7);
                int d0c = db + 16 * fp + ((lane >> 4) << 3);
                uint32_t baddr = sX + (uint32_t)brm * 256 + ((((d0c >> 3) ^ (brm & 7)) & 15) << 4);
                uint32_t bh4[4], bl4[4];
                ldsm_x4t(bh4, baddr);
                ldsm_x4t(bl4, baddr + 32768);
                mma_bf16(C2[2*fp],   ah, bh4);
                mma_bf16(C2[2*fp],   ah, bl4);
                mma_bf16(C2[2*fp+1], ah, bh4 + 2);
                mma_bf16(C2[2*fp+1], ah, bl4 + 2);
            }
        }
        CP_WAIT0();
        __syncthreads();
    }

    // ---- epilogue: counts ----
    float* scnt = (float*)(sm + OFF_CNT);
    #pragma unroll
    for (int j = 0; j < 16; j++) {
        cacc[j] += __shfl_xor_sync(0xffffffffu, cacc[j], 4);
        cacc[j] += __shfl_xor_sync(0xffffffffu, cacc[j], 8);
        cacc[j] += __shfl_xor_sync(0xffffffffu, cacc[j], 16);
    }
    if (lane < 4) {
        #pragma unroll
        for (int f = 0; f < 8; f++) {
            scnt[w * 64 + 8 * f + 2 * lane]     = cacc[2*f];
            scnt[w * 64 + 8 * f + 2 * lane + 1] = cacc[2*f+1];
        }
    }
    __syncthreads();
    if (tid < K) {
        float c = 0.0f;
        #pragma unroll
        for (int ww = 0; ww < 8; ww++) c += scnt[ww * 64 + tid];
        atomicAdd(&g_cc[(it + 1) * K + tid], c);
    }
    // ---- epilogue: mean via atomics into next slot ----
    float* gm = g_mu_raw + (size_t)(it + 1) * (K * D);
    #pragma unroll
    for (int f = 0; f < 8; f++) {
        int d0 = db + 8 * f + 2 * j2;
        atomicAdd(&gm[(kc0 + g) * D + d0],         C2[f][0]);
        atomicAdd(&gm[(kc0 + g) * D + d0 + 1],     C2[f][1]);
        atomicAdd(&gm[(kc0 + g + 8) * D + d0],     C2[f][2]);
        atomicAdd(&gm[(kc0 + g + 8) * D + d0 + 1], C2[f][3]);
    }
}

// ---------------------------------------------------------------------------
extern "C" void kernel_launch(void* const* d_in, const int* in_sizes, int n_in,
                              void* d_out, int out_size) {
    const float* embeds = (const float*)d_in[0];
    const float* init   = (const float*)d_in[1];
    int N = in_sizes[0] / D;
    int nT = (N + TILE - 1) / TILE;
    if (nT > NT_MAX) nT = NT_MAX;
    float* out_mu = (float*)d_out;
    float* out_r  = (float*)d_out + K * D;

    cudaFuncSetAttribute(iter_kernel<false>, cudaFuncAttributeMaxDynamicSharedMemorySize, SMEM_TOTAL);
    cudaFuncSetAttribute(iter_kernel<true>,  cudaFuncAttributeMaxDynamicSharedMemorySize, SMEM_TOTAL);

    int rowsPad = nT * TILE;
    prep_kernel<<<(rowsPad + 7) / 8, 256>>>(embeds, N, rowsPad);
    zero_kernel<<<(ITERS * K * D + 511) / 512, 512>>>();

    for (int it = 0; it < ITERS; it++) {
        if (it == ITERS - 1)
            iter_kernel<true><<<NB, 256, SMEM_TOTAL>>>(out_r, init, N, nT, it);
        else
            iter_kernel<false><<<NB, 256, SMEM_TOTAL>>>(nullptr, init, N, nT, it);
    }
    final_mu_kernel<<<K, 128>>>(out_mu);
}